// round 11
// baseline (speedup 1.0000x reference)
#include <cuda_runtime.h>
#include <cstdint>

#define NB    32
#define NMEL  128
#define TT    8192
#define NKEYS 88
#define NSLOT 57

// 57 distinct mel bins used by the 88 keys (validated rel_err 0.0, R1..R9)
__device__ constexpr int DBIN[NSLOT] = {
   1,  2,  3,  4,  5,  6,  7,  8,  9, 10, 11, 12, 13, 14, 15, 16, 17,
  19, 20, 21, 22, 23, 25, 26, 28, 29, 31, 33, 35, 37, 39, 42,
  44, 46, 49, 51, 53, 56, 58, 60, 63,
  65, 68, 70, 72, 75, 77, 79, 82, 84, 86, 89, 91, 93, 96, 98, 101
};

// key -> distinct-slot index (non-decreasing)
__device__ constexpr int KS[NKEYS] = {
   0, 0, 0, 0, 0,
   1, 1, 1, 1, 1, 1, 1, 1, 1,
   2, 2, 2, 2, 2, 2,
   3, 3, 3, 3,
   4, 4, 4,  5, 5, 5,  6, 6, 6,
   7, 7,  8, 8,  9, 9,
  10, 11, 11, 12, 13, 14, 15, 16, 16,
  17, 18, 19, 20, 21, 22, 23, 24, 25, 26, 27, 28, 29, 30, 31, 32,
  33, 34, 35, 36, 37, 38, 39, 40, 41, 42, 43, 44, 45, 46, 47, 48,
  49, 50, 51, 52, 53, 54, 55, 56
};

// slot -> [first key, last key)
__device__ constexpr int KST[NSLOT + 1] = {
   0,  5, 14, 20, 24, 27, 30, 33, 35, 37, 39, 40, 42, 43, 44, 45, 46, 48,
  49, 50, 51, 52, 53, 54, 55, 56, 57, 58, 59, 60, 61, 62, 63, 64, 65, 66,
  67, 68, 69, 70, 71, 72, 73, 74, 75, 76, 77, 78, 79, 80, 81, 82, 83, 84,
  85, 86, 87, 88
};

template <bool WRITE_TWO>
__global__ void __launch_bounds__(128, 5)
hps_key_probs_kernel(const float* __restrict__ mel,
                     float* __restrict__ out)
{
    // mask staging: [pass][tid][word], 4KB
    __shared__ uint32_t smask[4][128][2];

    const int b     = blockIdx.x >> 4;            // 16 blocks per batch
    const int tbase = (blockIdx.x & 15) * 512;    // 512 t-points per block

    // ---- 4 scalar passes, lanes strided by 128 t (coalesced loads).
    // Each pass = validated R8 pipeline: w[57] in regs -> selection -> cut,
    // then compress the 57 slot outcomes into a 57-bit mask.
    #pragma unroll 1
    for (int pass = 0; pass < 4; ++pass) {
        const int t = tbase + pass * 128 + (int)threadIdx.x;
        const float* __restrict__ mb = mel + (size_t)b * (NMEL * TT) + t;

        // log-domain HPS slot values (exp dropped by monotonicity; validated)
        float w[NSLOT];
        #pragma unroll
        for (int j = 0; j < NSLOT; ++j) {
            const int bn = DBIN[j];
            float s = __ldcs(mb + (size_t)bn * TT);
            if (bn < 64) s += __ldcs(mb + (size_t)(2 * bn) * TT);
            if (bn < 43) s += __ldcs(mb + (size_t)(3 * bn) * TT);
            w[j] = s;
        }

        float tt[16], g[16];

        // groups 0..4: bitonic sort-16 + merge-keep-top-16
        #pragma unroll
        for (int grp = 0; grp < 5; ++grp) {
            #pragma unroll
            for (int u = 0; u < 16; ++u) g[u] = w[KS[grp * 16 + u]];
            #pragma unroll
            for (int kk = 2; kk <= 16; kk <<= 1) {
                #pragma unroll
                for (int j = kk >> 1; j > 0; j >>= 1) {
                    #pragma unroll
                    for (int i = 0; i < 16; ++i) {
                        const int l = i ^ j;
                        if (l > i) {
                            const float a = g[i], c = g[l];
                            if ((i & kk) == 0) { g[i] = fmaxf(a, c); g[l] = fminf(a, c); }
                            else               { g[i] = fminf(a, c); g[l] = fmaxf(a, c); }
                        }
                    }
                }
            }
            if (grp == 0) {
                #pragma unroll
                for (int i = 0; i < 16; ++i) tt[i] = g[i];
            } else {
                #pragma unroll
                for (int i = 0; i < 16; ++i) tt[i] = fmaxf(tt[i], g[15 - i]);
                #pragma unroll
                for (int j = 8; j > 0; j >>= 1) {
                    #pragma unroll
                    for (int i = 0; i < 16; ++i) {
                        const int l = i ^ j;
                        if (l > i) {
                            const float a = tt[i], c = tt[l];
                            tt[i] = fmaxf(a, c); tt[l] = fminf(a, c);
                        }
                    }
                }
            }
        }

        // tail group (8 keys) + rank-13 extraction (validated R6..R9)
        float cut;
        {
            #pragma unroll
            for (int u = 0; u < 8; ++u) g[u] = w[KS[80 + u]];
            #pragma unroll
            for (int kk = 2; kk <= 8; kk <<= 1) {
                #pragma unroll
                for (int j = kk >> 1; j > 0; j >>= 1) {
                    #pragma unroll
                    for (int i = 0; i < 8; ++i) {
                        const int l = i ^ j;
                        if (l > i) {
                            const float a = g[i], c = g[l];
                            if ((i & kk) == 0) { g[i] = fmaxf(a, c); g[l] = fminf(a, c); }
                            else               { g[i] = fminf(a, c); g[l] = fmaxf(a, c); }
                        }
                    }
                }
            }
            #pragma unroll
            for (int i = 8; i < 16; ++i) tt[i] = fmaxf(tt[i], g[15 - i]);
            float l8[8];
            #pragma unroll
            for (int i = 0; i < 8; ++i) l8[i] = fminf(tt[i], tt[i + 8]);
            float l4[4];
            #pragma unroll
            for (int i = 0; i < 4; ++i) l4[i] = fminf(l8[i], l8[i + 4]);
            cut = fminf(fmaxf(l4[0], l4[2]), fmaxf(l4[1], l4[3]));
        }

        // pack outcomes into 57-bit mask
        uint32_t m0 = 0, m1 = 0;
        #pragma unroll
        for (int j = 0; j < 32; ++j)
            if (w[j] >= cut) m0 |= (1u << j);
        #pragma unroll
        for (int j = 32; j < NSLOT; ++j)
            if (w[j] >= cut) m1 |= (1u << (j - 32));

        smask[pass][threadIdx.x][0] = m0;
        smask[pass][threadIdx.x][1] = m1;
    }

    __syncthreads();

    // ---- Store phase: thread owns 4 consecutive t; gather the 4 masks,
    // decode per slot to a float4 of {0,1}, fan out STG.128 to contiguous
    // keys, both output copies.
    uint32_t M0[4], M1[4];
    #pragma unroll
    for (int r = 0; r < 4; ++r) {
        const int idx = (int)threadIdx.x * 4 + r;    // t-offset within block
        M0[r] = smask[idx >> 7][idx & 127][0];
        M1[r] = smask[idx >> 7][idx & 127][1];
    }

    float* o0 = out + (size_t)b * (NKEYS * TT) + tbase + (size_t)threadIdx.x * 4;
    const size_t half = (size_t)NB * NKEYS * TT;

    #pragma unroll
    for (int j = 0; j < NSLOT; ++j) {
        float4 pv;
        if (j < 32) {
            pv.x = __uint_as_float(((M0[0] >> j) & 1u) * 0x3F800000u);
            pv.y = __uint_as_float(((M0[1] >> j) & 1u) * 0x3F800000u);
            pv.z = __uint_as_float(((M0[2] >> j) & 1u) * 0x3F800000u);
            pv.w = __uint_as_float(((M0[3] >> j) & 1u) * 0x3F800000u);
        } else {
            pv.x = __uint_as_float(((M1[0] >> (j - 32)) & 1u) * 0x3F800000u);
            pv.y = __uint_as_float(((M1[1] >> (j - 32)) & 1u) * 0x3F800000u);
            pv.z = __uint_as_float(((M1[2] >> (j - 32)) & 1u) * 0x3F800000u);
            pv.w = __uint_as_float(((M1[3] >> (j - 32)) & 1u) * 0x3F800000u);
        }
        #pragma unroll
        for (int k = KST[j]; k < KST[j + 1]; ++k) {
            __stcs((float4*)(o0 + (size_t)k * TT), pv);
            if (WRITE_TWO) __stcs((float4*)(o0 + (size_t)k * TT + half), pv);
        }
    }
}

extern "C" void kernel_launch(void* const* d_in, const int* in_sizes, int n_in,
                              void* d_out, int out_size)
{
    const float* mel = (const float*)d_in[0];
    float* out = (float*)d_out;
    const long long half = (long long)NB * NKEYS * TT;   // 23,068,672

    const int blocks = NB * TT / 512;    // 512 t-points per block -> 512 blocks
    if (out_size >= 2 * half)
        hps_key_probs_kernel<true><<<blocks, 128>>>(mel, out);
    else
        hps_key_probs_kernel<false><<<blocks, 128>>>(mel, out);
}

// round 12
// speedup vs baseline: 1.1454x; 1.1454x over previous
#include <cuda_runtime.h>
#include <cstdint>

#define NB    32
#define NMEL  128
#define TT    8192
#define NKEYS 88
#define NSLOT 57

// 57 distinct mel bins used by the 88 keys (validated rel_err 0.0, R1..R10)
__device__ constexpr int DBIN[NSLOT] = {
   1,  2,  3,  4,  5,  6,  7,  8,  9, 10, 11, 12, 13, 14, 15, 16, 17,
  19, 20, 21, 22, 23, 25, 26, 28, 29, 31, 33, 35, 37, 39, 42,
  44, 46, 49, 51, 53, 56, 58, 60, 63,
  65, 68, 70, 72, 75, 77, 79, 82, 84, 86, 89, 91, 93, 96, 98, 101
};

// key -> distinct-slot index (compile-time use in the network)
__device__ constexpr int KS[NKEYS] = {
   0, 0, 0, 0, 0,
   1, 1, 1, 1, 1, 1, 1, 1, 1,
   2, 2, 2, 2, 2, 2,
   3, 3, 3, 3,
   4, 4, 4,  5, 5, 5,  6, 6, 6,
   7, 7,  8, 8,  9, 9,
  10, 11, 11, 12, 13, 14, 15, 16, 16,
  17, 18, 19, 20, 21, 22, 23, 24, 25, 26, 27, 28, 29, 30, 31, 32,
  33, 34, 35, 36, 37, 38, 39, 40, 41, 42, 43, 44, 45, 46, 47, 48,
  49, 50, 51, 52, 53, 54, 55, 56
};

// runtime key -> slot lookup for the store phase (constant bank, LDC)
__constant__ int KSLOT_C[NKEYS] = {
   0, 0, 0, 0, 0,
   1, 1, 1, 1, 1, 1, 1, 1, 1,
   2, 2, 2, 2, 2, 2,
   3, 3, 3, 3,
   4, 4, 4,  5, 5, 5,  6, 6, 6,
   7, 7,  8, 8,  9, 9,
  10, 11, 11, 12, 13, 14, 15, 16, 16,
  17, 18, 19, 20, 21, 22, 23, 24, 25, 26, 27, 28, 29, 30, 31, 32,
  33, 34, 35, 36, 37, 38, 39, 40, 41, 42, 43, 44, 45, 46, 47, 48,
  49, 50, 51, 52, 53, 54, 55, 56
};

template <bool WRITE_TWO>
__global__ void __launch_bounds__(128, 5)
hps_key_probs_kernel(const float* __restrict__ mel,
                     float* __restrict__ out)
{
    // 57-bit outcome mask per thread: [word][tid] to soften store-phase LDS
    // conflicts. 1KB.
    __shared__ uint32_t smask[2][128];

    const int p = blockIdx.x * 128 + (int)threadIdx.x;   // 0..262143
    const int b = p >> 13;
    const int t = p & (TT - 1);
    const int tbase = t & ~127;                           // block's t window

    const float* __restrict__ mb = mel + (size_t)b * (NMEL * TT) + t;

    // ---- Compute phase: identical to R8 (best: 43.8us, DRAM 62.9%).
    float w[NSLOT];
    #pragma unroll
    for (int j = 0; j < NSLOT; ++j) {
        const int bn = DBIN[j];
        float s = __ldcs(mb + (size_t)bn * TT);
        if (bn < 64) s += __ldcs(mb + (size_t)(2 * bn) * TT);
        if (bn < 43) s += __ldcs(mb + (size_t)(3 * bn) * TT);
        w[j] = s;
    }

    float tt[16], g[16];

    #pragma unroll
    for (int grp = 0; grp < 5; ++grp) {
        #pragma unroll
        for (int u = 0; u < 16; ++u) g[u] = w[KS[grp * 16 + u]];
        #pragma unroll
        for (int kk = 2; kk <= 16; kk <<= 1) {
            #pragma unroll
            for (int j = kk >> 1; j > 0; j >>= 1) {
                #pragma unroll
                for (int i = 0; i < 16; ++i) {
                    const int l = i ^ j;
                    if (l > i) {
                        const float a = g[i], c = g[l];
                        if ((i & kk) == 0) { g[i] = fmaxf(a, c); g[l] = fminf(a, c); }
                        else               { g[i] = fminf(a, c); g[l] = fmaxf(a, c); }
                    }
                }
            }
        }
        if (grp == 0) {
            #pragma unroll
            for (int i = 0; i < 16; ++i) tt[i] = g[i];
        } else {
            #pragma unroll
            for (int i = 0; i < 16; ++i) tt[i] = fmaxf(tt[i], g[15 - i]);
            #pragma unroll
            for (int j = 8; j > 0; j >>= 1) {
                #pragma unroll
                for (int i = 0; i < 16; ++i) {
                    const int l = i ^ j;
                    if (l > i) {
                        const float a = tt[i], c = tt[l];
                        tt[i] = fmaxf(a, c); tt[l] = fminf(a, c);
                    }
                }
            }
        }
    }

    float cut;
    {
        #pragma unroll
        for (int u = 0; u < 8; ++u) g[u] = w[KS[80 + u]];
        #pragma unroll
        for (int kk = 2; kk <= 8; kk <<= 1) {
            #pragma unroll
            for (int j = kk >> 1; j > 0; j >>= 1) {
                #pragma unroll
                for (int i = 0; i < 8; ++i) {
                    const int l = i ^ j;
                    if (l > i) {
                        const float a = g[i], c = g[l];
                        if ((i & kk) == 0) { g[i] = fmaxf(a, c); g[l] = fminf(a, c); }
                        else               { g[i] = fminf(a, c); g[l] = fmaxf(a, c); }
                    }
                }
            }
        }
        #pragma unroll
        for (int i = 8; i < 16; ++i) tt[i] = fmaxf(tt[i], g[15 - i]);
        float l8[8];
        #pragma unroll
        for (int i = 0; i < 8; ++i) l8[i] = fminf(tt[i], tt[i + 8]);
        float l4[4];
        #pragma unroll
        for (int i = 0; i < 4; ++i) l4[i] = fminf(l8[i], l8[i + 4]);
        cut = fminf(fmaxf(l4[0], l4[2]), fmaxf(l4[1], l4[3]));
    }

    // ---- Pack outcomes into a 57-bit mask and hand off via smem.
    {
        uint32_t m0 = 0, m1 = 0;
        #pragma unroll
        for (int j = 0; j < 32; ++j)
            if (w[j] >= cut) m0 |= (1u << j);
        #pragma unroll
        for (int j = 32; j < NSLOT; ++j)
            if (w[j] >= cut) m1 |= (1u << (j - 32));
        smask[0][threadIdx.x] = m0;
        smask[1][threadIdx.x] = m1;
    }
    __syncthreads();

    // ---- Store phase: 176 key-rows (88 x 2 copies) x 32 quads, one STG.128
    // per item. Warp wid handles rows {wid, wid+4, ...}; lane owns quad=lane
    // (4 consecutive t) -> each warp-store is one coalesced 512B line.
    const int lane = (int)threadIdx.x & 31;
    const int wid  = (int)threadIdx.x >> 5;

    uint32_t M0[4], M1[4];
    #pragma unroll
    for (int r = 0; r < 4; ++r) {
        M0[r] = smask[0][4 * lane + r];
        M1[r] = smask[1][4 * lane + r];
    }

    float* obase = out + (size_t)b * (NKEYS * TT) + tbase + lane * 4;
    const size_t half = (size_t)NB * NKEYS * TT;
    const int nrows = WRITE_TWO ? 176 : 88;

    #pragma unroll 4
    for (int row = wid; row < nrows; row += 4) {
        const int k = (row < NKEYS) ? row : row - NKEYS;
        const int j = KSLOT_C[k];
        const uint32_t sh = (uint32_t)j & 31u;
        const bool hiw = (j >= 32);
        float4 pv;
        pv.x = __uint_as_float((((hiw ? M1[0] : M0[0]) >> sh) & 1u) * 0x3F800000u);
        pv.y = __uint_as_float((((hiw ? M1[1] : M0[1]) >> sh) & 1u) * 0x3F800000u);
        pv.z = __uint_as_float((((hiw ? M1[2] : M0[2]) >> sh) & 1u) * 0x3F800000u);
        pv.w = __uint_as_float((((hiw ? M1[3] : M0[3]) >> sh) & 1u) * 0x3F800000u);
        const size_t off = (size_t)k * TT + ((row < NKEYS) ? 0 : half);
        __stcs((float4*)(obase + off), pv);
    }
}

extern "C" void kernel_launch(void* const* d_in, const int* in_sizes, int n_in,
                              void* d_out, int out_size)
{
    const float* mel = (const float*)d_in[0];
    float* out = (float*)d_out;
    const long long half = (long long)NB * NKEYS * TT;   // 23,068,672
    const int points = NB * TT;                          // 262144

    if (out_size >= 2 * half)
        hps_key_probs_kernel<true><<<points / 128, 128>>>(mel, out);
    else
        hps_key_probs_kernel<false><<<points / 128, 128>>>(mel, out);
}

// round 13
// speedup vs baseline: 1.1842x; 1.0339x over previous
#include <cuda_runtime.h>
#include <cstdint>

#define NB    32
#define NMEL  128
#define TT    8192
#define NKEYS 88
#define NSLOT 57

// 57 distinct mel bins used by the 88 keys (validated rel_err 0.0, R1..R11)
__device__ constexpr int DBIN[NSLOT] = {
   1,  2,  3,  4,  5,  6,  7,  8,  9, 10, 11, 12, 13, 14, 15, 16, 17,
  19, 20, 21, 22, 23, 25, 26, 28, 29, 31, 33, 35, 37, 39, 42,
  44, 46, 49, 51, 53, 56, 58, 60, 63,
  65, 68, 70, 72, 75, 77, 79, 82, 84, 86, 89, 91, 93, 96, 98, 101
};

// key -> distinct-slot index (non-decreasing)
__device__ constexpr int KS[NKEYS] = {
   0, 0, 0, 0, 0,
   1, 1, 1, 1, 1, 1, 1, 1, 1,
   2, 2, 2, 2, 2, 2,
   3, 3, 3, 3,
   4, 4, 4,  5, 5, 5,  6, 6, 6,
   7, 7,  8, 8,  9, 9,
  10, 11, 11, 12, 13, 14, 15, 16, 16,
  17, 18, 19, 20, 21, 22, 23, 24, 25, 26, 27, 28, 29, 30, 31, 32,
  33, 34, 35, 36, 37, 38, 39, 40, 41, 42, 43, 44, 45, 46, 47, 48,
  49, 50, 51, 52, 53, 54, 55, 56
};

// slot -> [first key, last key).  Note: slot 13 = {43}, slot 14 = {44}:
// keys 0..43 <-> slots 0..13, keys 44..87 <-> slots 14..56 (clean half split).
__device__ constexpr int KST[NSLOT + 1] = {
   0,  5, 14, 20, 24, 27, 30, 33, 35, 37, 39, 40, 42, 43, 44, 45, 46, 48,
  49, 50, 51, 52, 53, 54, 55, 56, 57, 58, 59, 60, 61, 62, 63, 64, 65, 66,
  67, 68, 69, 70, 71, 72, 73, 74, 75, 76, 77, 78, 79, 80, 81, 82, 83, 84,
  85, 86, 87, 88
};

template <bool WRITE_TWO>
__global__ void __launch_bounds__(128, 5)
hps_key_probs_kernel(const float* __restrict__ mel,
                     float* __restrict__ out)
{
    __shared__ uint32_t smask[2][128];   // 57-bit outcome mask per thread, 1KB

    const int p = blockIdx.x * 128 + (int)threadIdx.x;   // 0..262143
    const int b = p >> 13;
    const int t = p & (TT - 1);
    const int tbase = t & ~127;                           // block's t window

    const float* __restrict__ mb = mel + (size_t)b * (NMEL * TT) + t;

    // ---- Compute phase: identical to R8 (best compute config: DRAM 62.9%).
    float w[NSLOT];
    #pragma unroll
    for (int j = 0; j < NSLOT; ++j) {
        const int bn = DBIN[j];
        float s = __ldcs(mb + (size_t)bn * TT);
        if (bn < 64) s += __ldcs(mb + (size_t)(2 * bn) * TT);
        if (bn < 43) s += __ldcs(mb + (size_t)(3 * bn) * TT);
        w[j] = s;
    }

    float tt[16], g[16];

    #pragma unroll
    for (int grp = 0; grp < 5; ++grp) {
        #pragma unroll
        for (int u = 0; u < 16; ++u) g[u] = w[KS[grp * 16 + u]];
        #pragma unroll
        for (int kk = 2; kk <= 16; kk <<= 1) {
            #pragma unroll
            for (int j = kk >> 1; j > 0; j >>= 1) {
                #pragma unroll
                for (int i = 0; i < 16; ++i) {
                    const int l = i ^ j;
                    if (l > i) {
                        const float a = g[i], c = g[l];
                        if ((i & kk) == 0) { g[i] = fmaxf(a, c); g[l] = fminf(a, c); }
                        else               { g[i] = fminf(a, c); g[l] = fmaxf(a, c); }
                    }
                }
            }
        }
        if (grp == 0) {
            #pragma unroll
            for (int i = 0; i < 16; ++i) tt[i] = g[i];
        } else {
            #pragma unroll
            for (int i = 0; i < 16; ++i) tt[i] = fmaxf(tt[i], g[15 - i]);
            #pragma unroll
            for (int j = 8; j > 0; j >>= 1) {
                #pragma unroll
                for (int i = 0; i < 16; ++i) {
                    const int l = i ^ j;
                    if (l > i) {
                        const float a = tt[i], c = tt[l];
                        tt[i] = fmaxf(a, c); tt[l] = fminf(a, c);
                    }
                }
            }
        }
    }

    float cut;
    {
        #pragma unroll
        for (int u = 0; u < 8; ++u) g[u] = w[KS[80 + u]];
        #pragma unroll
        for (int kk = 2; kk <= 8; kk <<= 1) {
            #pragma unroll
            for (int j = kk >> 1; j > 0; j >>= 1) {
                #pragma unroll
                for (int i = 0; i < 8; ++i) {
                    const int l = i ^ j;
                    if (l > i) {
                        const float a = g[i], c = g[l];
                        if ((i & kk) == 0) { g[i] = fmaxf(a, c); g[l] = fminf(a, c); }
                        else               { g[i] = fminf(a, c); g[l] = fmaxf(a, c); }
                    }
                }
            }
        }
        #pragma unroll
        for (int i = 8; i < 16; ++i) tt[i] = fmaxf(tt[i], g[15 - i]);
        float l8[8];
        #pragma unroll
        for (int i = 0; i < 8; ++i) l8[i] = fminf(tt[i], tt[i + 8]);
        float l4[4];
        #pragma unroll
        for (int i = 0; i < 4; ++i) l4[i] = fminf(l8[i], l8[i + 4]);
        cut = fminf(fmaxf(l4[0], l4[2]), fmaxf(l4[1], l4[3]));
    }

    // ---- Pack outcomes into a 57-bit mask, hand off via smem.
    {
        uint32_t m0 = 0, m1 = 0;
        #pragma unroll
        for (int j = 0; j < 32; ++j)
            if (w[j] >= cut) m0 |= (1u << j);
        #pragma unroll
        for (int j = 32; j < NSLOT; ++j)
            if (w[j] >= cut) m1 |= (1u << (j - 32));
        smask[0][threadIdx.x] = m0;
        smask[1][threadIdx.x] = m1;
    }
    __syncthreads();

    // ---- Store phase: lane owns quad = lane (4 consecutive t of the 128-t
    // window); warp w: copy = w&1, key-half = w>>1. Slot loops are fully
    // compile-time: decode once per slot (SHF-imm+LOP3 on alu, IMAD-imm on
    // the idle fma pipe), reuse the float4 across the slot's key fan-out.
    const int lane = (int)threadIdx.x & 31;
    const int wid  = (int)threadIdx.x >> 5;
    const int cpy  = wid & 1;
    const int hlf  = wid >> 1;

    if (!WRITE_TWO && cpy) return;   // no syncs after this point

    uint32_t M0[4], M1[4];
    #pragma unroll
    for (int r = 0; r < 4; ++r) {
        M0[r] = smask[0][4 * lane + r];
        M1[r] = smask[1][4 * lane + r];
    }

    const size_t half = (size_t)NB * NKEYS * TT;
    float* obase = out + (size_t)b * (NKEYS * TT) + tbase + lane * 4
                 + (cpy ? half : 0);

    if (hlf == 0) {
        // slots 0..13 -> keys 0..43 (14 decodes, 44 STG.128)
        #pragma unroll
        for (int j = 0; j < 14; ++j) {
            float4 pv;
            pv.x = __uint_as_float(((M0[0] >> j) & 1u) * 0x3F800000u);
            pv.y = __uint_as_float(((M0[1] >> j) & 1u) * 0x3F800000u);
            pv.z = __uint_as_float(((M0[2] >> j) & 1u) * 0x3F800000u);
            pv.w = __uint_as_float(((M0[3] >> j) & 1u) * 0x3F800000u);
            #pragma unroll
            for (int k = KST[j]; k < KST[j + 1]; ++k)
                __stcs((float4*)(obase + (size_t)k * TT), pv);
        }
    } else {
        // slots 14..56 -> keys 44..87 (43 decodes, 44 STG.128)
        #pragma unroll
        for (int j = 14; j < NSLOT; ++j) {
            float4 pv;
            if (j < 32) {
                pv.x = __uint_as_float(((M0[0] >> j) & 1u) * 0x3F800000u);
                pv.y = __uint_as_float(((M0[1] >> j) & 1u) * 0x3F800000u);
                pv.z = __uint_as_float(((M0[2] >> j) & 1u) * 0x3F800000u);
                pv.w = __uint_as_float(((M0[3] >> j) & 1u) * 0x3F800000u);
            } else {
                pv.x = __uint_as_float(((M1[0] >> (j - 32)) & 1u) * 0x3F800000u);
                pv.y = __uint_as_float(((M1[1] >> (j - 32)) & 1u) * 0x3F800000u);
                pv.z = __uint_as_float(((M1[2] >> (j - 32)) & 1u) * 0x3F800000u);
                pv.w = __uint_as_float(((M1[3] >> (j - 32)) & 1u) * 0x3F800000u);
            }
            #pragma unroll
            for (int k = KST[j]; k < KST[j + 1]; ++k)
                __stcs((float4*)(obase + (size_t)k * TT), pv);
        }
    }
}

extern "C" void kernel_launch(void* const* d_in, const int* in_sizes, int n_in,
                              void* d_out, int out_size)
{
    const float* mel = (const float*)d_in[0];
    float* out = (float*)d_out;
    const long long half = (long long)NB * NKEYS * TT;   // 23,068,672
    const int points = NB * TT;                          // 262144

    if (out_size >= 2 * half)
        hps_key_probs_kernel<true><<<points / 128, 128>>>(mel, out);
    else
        hps_key_probs_kernel<false><<<points / 128, 128>>>(mel, out);
}

// round 14
// speedup vs baseline: 1.2126x; 1.0240x over previous
#include <cuda_runtime.h>

#define NB    32
#define NMEL  128
#define TT    8192
#define NKEYS 88
#define NSLOT 57

// 57 distinct mel bins used by the 88 keys (validated rel_err 0.0, R1..R12)
__device__ constexpr int DBIN[NSLOT] = {
   1,  2,  3,  4,  5,  6,  7,  8,  9, 10, 11, 12, 13, 14, 15, 16, 17,
  19, 20, 21, 22, 23, 25, 26, 28, 29, 31, 33, 35, 37, 39, 42,
  44, 46, 49, 51, 53, 56, 58, 60, 63,
  65, 68, 70, 72, 75, 77, 79, 82, 84, 86, 89, 91, 93, 96, 98, 101
};

// key -> distinct-slot index (non-decreasing)
__device__ constexpr int KS[NKEYS] = {
   0, 0, 0, 0, 0,
   1, 1, 1, 1, 1, 1, 1, 1, 1,
   2, 2, 2, 2, 2, 2,
   3, 3, 3, 3,
   4, 4, 4,  5, 5, 5,  6, 6, 6,
   7, 7,  8, 8,  9, 9,
  10, 11, 11, 12, 13, 14, 15, 16, 16,
  17, 18, 19, 20, 21, 22, 23, 24, 25, 26, 27, 28, 29, 30, 31, 32,
  33, 34, 35, 36, 37, 38, 39, 40, 41, 42, 43, 44, 45, 46, 47, 48,
  49, 50, 51, 52, 53, 54, 55, 56
};

// slot -> [first key, last key)
__device__ constexpr int KST[NSLOT + 1] = {
   0,  5, 14, 20, 24, 27, 30, 33, 35, 37, 39, 40, 42, 43, 44, 45, 46, 48,
  49, 50, 51, 52, 53, 54, 55, 56, 57, 58, 59, 60, 61, 62, 63, 64, 65, 66,
  67, 68, 69, 70, 71, 72, 73, 74, 75, 76, 77, 78, 79, 80, 81, 82, 83, 84,
  85, 86, 87, 88
};

template <bool WRITE_TWO>
__global__ void __launch_bounds__(128, 5)
hps_key_probs_kernel(const float* __restrict__ mel,
                     float* __restrict__ out)
{
    const int p = blockIdx.x * 128 + threadIdx.x;   // 0..262143
    const int b = p >> 13;
    const int t = p & (TT - 1);

    const float* __restrict__ mb = mel + (size_t)b * (NMEL * TT) + t;

    // ---- Load all 57 distinct slot values into registers (log-domain HPS:
    // m[bin] (+ m[2bin]) (+ m[3bin]); exp dropped by monotonicity, validated).
    // __ldcs: single-use data, evict-first keeps L2 free for the write stream.
    float w[NSLOT];
    #pragma unroll
    for (int j = 0; j < NSLOT; ++j) {
        const int bn = DBIN[j];
        float s = __ldcs(mb + (size_t)bn * TT);
        if (bn < 64) s += __ldcs(mb + (size_t)(2 * bn) * TT);
        if (bn < 43) s += __ldcs(mb + (size_t)(3 * bn) * TT);
        w[j] = s;
    }

    float tt[16], g[16];

    // ---- Streaming selection of the 14th-largest of the 88-multiset.
    // Groups 0..4: 16 keys each.
    #pragma unroll
    for (int grp = 0; grp < 5; ++grp) {
        #pragma unroll
        for (int u = 0; u < 16; ++u) g[u] = w[KS[grp * 16 + u]];
        // bitonic sort-16 descending (compile-time lanes)
        #pragma unroll
        for (int kk = 2; kk <= 16; kk <<= 1) {
            #pragma unroll
            for (int j = kk >> 1; j > 0; j >>= 1) {
                #pragma unroll
                for (int i = 0; i < 16; ++i) {
                    const int l = i ^ j;
                    if (l > i) {
                        const float a = g[i], c = g[l];
                        if ((i & kk) == 0) { g[i] = fmaxf(a, c); g[l] = fminf(a, c); }
                        else               { g[i] = fminf(a, c); g[l] = fmaxf(a, c); }
                    }
                }
            }
        }
        if (grp == 0) {
            #pragma unroll
            for (int i = 0; i < 16; ++i) tt[i] = g[i];
        } else {
            // merge-keep-top-16: max vs reversed g (bitonic) then clean
            #pragma unroll
            for (int i = 0; i < 16; ++i) tt[i] = fmaxf(tt[i], g[15 - i]);
            #pragma unroll
            for (int j = 8; j > 0; j >>= 1) {
                #pragma unroll
                for (int i = 0; i < 16; ++i) {
                    const int l = i ^ j;
                    if (l > i) {
                        const float a = tt[i], c = tt[l];
                        tt[i] = fmaxf(a, c); tt[l] = fminf(a, c);
                    }
                }
            }
        }
    }

    // Tail group: 8 keys (80..87) -> sort-8, asym merge, rank-13 extraction
    // (validated rel_err 0.0, R6..R12).
    float cut;
    {
        #pragma unroll
        for (int u = 0; u < 8; ++u) g[u] = w[KS[80 + u]];
        #pragma unroll
        for (int kk = 2; kk <= 8; kk <<= 1) {
            #pragma unroll
            for (int j = kk >> 1; j > 0; j >>= 1) {
                #pragma unroll
                for (int i = 0; i < 8; ++i) {
                    const int l = i ^ j;
                    if (l > i) {
                        const float a = g[i], c = g[l];
                        if ((i & kk) == 0) { g[i] = fmaxf(a, c); g[l] = fminf(a, c); }
                        else               { g[i] = fminf(a, c); g[l] = fmaxf(a, c); }
                    }
                }
            }
        }
        // positions 8..15 absorb g[7..0]; 0..7 unchanged (pad = -inf)
        #pragma unroll
        for (int i = 8; i < 16; ++i) tt[i] = fmaxf(tt[i], g[15 - i]);
        // tt bitonic; descend to rank 13 (14th largest)
        float l8[8];
        #pragma unroll
        for (int i = 0; i < 8; ++i) l8[i] = fminf(tt[i], tt[i + 8]);
        float l4[4];
        #pragma unroll
        for (int i = 0; i < 4; ++i) l4[i] = fminf(l8[i], l8[i + 4]);
        const float p0 = fmaxf(l4[0], l4[2]);
        const float p1 = fmaxf(l4[1], l4[3]);
        cut = fminf(p0, p1);
    }

    float* o0 = out + (size_t)b * (NKEYS * TT) + t;
    const size_t half = (size_t)NB * NKEYS * TT;

    // ---- Output: one compare per slot, fan out to contiguous keys, both
    // copies (compile-time). __stcs: evict-first, stream dirty lines out.
    #pragma unroll
    for (int j = 0; j < NSLOT; ++j) {
        const float pv = (w[j] >= cut) ? 1.0f : 0.0f;
        #pragma unroll
        for (int k = KST[j]; k < KST[j + 1]; ++k) {
            __stcs(o0 + (size_t)k * TT, pv);
            if (WRITE_TWO) __stcs(o0 + (size_t)k * TT + half, pv);
        }
    }
}

extern "C" void kernel_launch(void* const* d_in, const int* in_sizes, int n_in,
                              void* d_out, int out_size)
{
    const float* mel = (const float*)d_in[0];
    float* out = (float*)d_out;
    const long long half = (long long)NB * NKEYS * TT;   // 23,068,672
    const int points = NB * TT;                          // 262144

    if (out_size >= 2 * half)
        hps_key_probs_kernel<true><<<points / 128, 128>>>(mel, out);
    else
        hps_key_probs_kernel<false><<<points / 128, 128>>>(mel, out);
}